// round 8
// baseline (speedup 1.0000x reference)
#include <cuda_runtime.h>
#include <cuda_bf16.h>
#include <math.h>
#include <stdint.h>

// ---------------- problem constants ----------------
#define Bsz    4
#define Cdim   256
#define Hh     128
#define Wd     128
#define Np     (Hh*Wd)        // 16384
#define CH3    (3*Cdim)       // 768
#define HID    680
#define HID2   1360
#define NHEADS 8
#define HD     32
#define SPLITS 128
#define CHUNK  (Np/SPLITS)    // 128

#define KPAD_G 704
#define MPAD_PIN 1408

// ---------------- scratch (device globals; no runtime alloc) ----------------
__device__ __align__(16) __nv_bfloat16 g_qkv [(size_t)Bsz*CH3 *Np];
__device__ __align__(16) __nv_bfloat16 g_qkv2[(size_t)Bsz*CH3 *Np];
__device__ float g_inv  [2*Bsz*Cdim];
__device__ float g_spart[(size_t)Bsz*NHEADS*SPLITS*HD*HD];
__device__ float g_attn [Bsz*NHEADS*HD*HD];
__device__ float g_x1   [(size_t)Bsz*Cdim*Np];
__device__ __align__(16) __nv_bfloat16 g_pin [(size_t)Bsz*HID2*Np];
__device__ __align__(16) __nv_bfloat16 g_gate[(size_t)Bsz*HID *Np];

// bf16 operand buffer (X, [b][n][K])
__device__ __align__(16) __nv_bfloat16 g_xh[(size_t)Bsz*Np*KPAD_G];
// weights: qkv(768*256) | po(256*256) | pin(1408*256) | pout(256*704)
#define WOFF_QKV  0
#define WOFF_PO   (768*256)
#define WOFF_PIN  (WOFF_PO + 256*256)
#define WOFF_POUT (WOFF_PIN + 1408*256)
#define WTOT      (WOFF_POUT + 256*704)
__device__ __align__(16) __nv_bfloat16 g_wh[WTOT];

// ---------------- PTX helpers ----------------
__device__ __forceinline__ uint32_t smem_u32(const void* p) {
    uint32_t a;
    asm("{ .reg .u64 t; cvta.to.shared.u64 t, %1; cvt.u32.u64 %0, t; }" : "=r"(a) : "l"(p));
    return a;
}
#define CP_ASYNC16(dst, src) \
    asm volatile("cp.async.cg.shared.global [%0], [%1], 16;" :: "r"(dst), "l"(src) : "memory")
#define CP_COMMIT() asm volatile("cp.async.commit_group;" ::: "memory")
#define CP_WAIT(n)  asm volatile("cp.async.wait_group %0;" :: "n"(n) : "memory")

__device__ __forceinline__ void ldsm4(uint32_t* r, uint32_t addr) {
    asm volatile("ldmatrix.sync.aligned.m8n8.x4.shared.b16 {%0,%1,%2,%3}, [%4];"
                 : "=r"(r[0]), "=r"(r[1]), "=r"(r[2]), "=r"(r[3]) : "r"(addr));
}
__device__ __forceinline__ void mma16816(float* c, const uint32_t* a, const uint32_t* b) {
    asm volatile(
        "mma.sync.aligned.m16n8k16.row.col.f32.bf16.bf16.f32 "
        "{%0,%1,%2,%3}, {%4,%5,%6,%7}, {%8,%9}, {%0,%1,%2,%3};"
        : "+f"(c[0]), "+f"(c[1]), "+f"(c[2]), "+f"(c[3])
        : "r"(a[0]), "r"(a[1]), "r"(a[2]), "r"(a[3]), "r"(b[0]), "r"(b[1]));
}
__device__ __forceinline__ uint32_t packbf2(float a, float b) {
    __nv_bfloat162 h = __floats2bfloat162_rn(a, b);
    return *(uint32_t*)&h;
}
__device__ __forceinline__ void unpack8(const uint4 v, float* r) {
    float2 f;
    f = __bfloat1622float2(*(const __nv_bfloat162*)&v.x); r[0] = f.x; r[1] = f.y;
    f = __bfloat1622float2(*(const __nv_bfloat162*)&v.y); r[2] = f.x; r[3] = f.y;
    f = __bfloat1622float2(*(const __nv_bfloat162*)&v.z); r[4] = f.x; r[5] = f.y;
    f = __bfloat1622float2(*(const __nv_bfloat162*)&v.w); r[6] = f.x; r[7] = f.y;
}
__device__ __forceinline__ void load_row10(float* r, const __nv_bfloat16* t,
                                           int row, int x0, bool valid) {
    if (!valid) {
        #pragma unroll
        for (int i = 0; i < 10; i++) r[i] = 0.f;
        return;
    }
    const __nv_bfloat16* p = t + row * 128;
    uint4 v = *(const uint4*)(p + x0);
    unpack8(v, r + 1);
    r[0] = (x0 > 0)   ? __bfloat162float(p[x0 - 1]) : 0.f;
    r[9] = (x0 < 120) ? __bfloat162float(p[x0 + 8]) : 0.f;
}

// ================= mma.sync GEMM bf16, 128x256 block tile, 3-stage pipeline =================
// W: [Mpad][Kpad] bf16 row-major; X: [b][n][Kpad] bf16. BK=32.
// 8 warps: warpM in {0,1} (64 rows), warpN in {0..3} (64 cols). Warp tile 64x64.
#define TA_B     10240          // A: 128 rows x 80 B
#define TB_B     20480          // B: 256 rows x 80 B
#define STAGE_B  (TA_B + TB_B)  // 30720
#define GEMM_SMEM (3*STAGE_B)   // 92160

__device__ __forceinline__ void gemm_issue_tile(
    uint32_t st, int tid, const __nv_bfloat16* Wh, const __nv_bfloat16* Xh_b,
    int rowBase, int Kpad, int k0)
{
    #pragma unroll
    for (int c = tid; c < 512; c += 256) {       // A: 128 rows x 64 B
        int r = c >> 2, cc = c & 3;
        CP_ASYNC16(st + r * 80 + cc * 16,
                   Wh + (size_t)(rowBase + r) * Kpad + k0 + cc * 8);
    }
    #pragma unroll
    for (int c = tid; c < 1024; c += 256) {      // B: 256 rows x 64 B
        int r = c >> 2, cc = c & 3;
        CP_ASYNC16(st + TA_B + r * 80 + cc * 16,
                   Xh_b + (size_t)r * Kpad + k0 + cc * 8);
    }
    CP_COMMIT();
}

template<bool OUT_BF16>
__global__ __launch_bounds__(256, 1) void gemm_mma_kernel(
    const __nv_bfloat16* __restrict__ Wh,
    const __nv_bfloat16* __restrict__ Xh,
    const float* __restrict__ bias, const float* __restrict__ res,
    void* __restrict__ outp, int M, int Kpad)
{
    extern __shared__ char smem[];
    const uint32_t sb = smem_u32(smem);
    const int tid = threadIdx.x, lane = tid & 31, wid = tid >> 5;
    const int warpM = wid & 1, warpN = wid >> 1;
    const int rowBase = blockIdx.y * 128, colBase = blockIdx.x * 256, b = blockIdx.z;

    const __nv_bfloat16* Xh_b = Xh + ((size_t)b * Np + colBase) * Kpad;

    float acc[4][8][4];
    #pragma unroll
    for (int i = 0; i < 4; i++)
        #pragma unroll
        for (int j = 0; j < 8; j++)
            #pragma unroll
            for (int k = 0; k < 4; k++) acc[i][j][k] = 0.f;

    const int nk = Kpad >> 5;
    gemm_issue_tile(sb,           tid, Wh, Xh_b, rowBase, Kpad, 0);
    gemm_issue_tile(sb + STAGE_B, tid, Wh, Xh_b, rowBase, Kpad, 32);

    for (int i = 0; i < nk; i++) {
        if (i + 2 < nk) {
            gemm_issue_tile(sb + ((i + 2) % 3) * STAGE_B, tid, Wh, Xh_b,
                            rowBase, Kpad, (i + 2) << 5);
            CP_WAIT(2);
        } else if (i + 1 < nk) {
            CP_WAIT(1);
        } else {
            CP_WAIT(0);
        }
        __syncthreads();

        const uint32_t st = sb + (i % 3) * STAGE_B;
        #pragma unroll
        for (int kk = 0; kk < 2; kk++) {
            uint32_t aA[4][4], bB[8][2];
            const int arow = lane & 15, ahalf = lane >> 4;
            #pragma unroll
            for (int mf = 0; mf < 4; mf++) {
                uint32_t ad = st + (uint32_t)(warpM * 64 + mf * 16 + arow) * 80
                              + kk * 32 + ahalf * 16;
                ldsm4(aA[mf], ad);
            }
            #pragma unroll
            for (int nfp = 0; nfp < 4; nfp++) {
                int nrow = warpN * 64 + nfp * 16 + ((lane >> 4) * 8 + (lane & 7));
                int kb = (lane >> 3) & 1;
                uint32_t bd = st + TA_B + (uint32_t)nrow * 80 + kk * 32 + kb * 16;
                uint32_t t[4];
                ldsm4(t, bd);
                bB[nfp*2][0] = t[0]; bB[nfp*2][1] = t[1];
                bB[nfp*2+1][0] = t[2]; bB[nfp*2+1][1] = t[3];
            }
            #pragma unroll
            for (int mf = 0; mf < 4; mf++)
                #pragma unroll
                for (int nf = 0; nf < 8; nf++)
                    mma16816(acc[mf][nf], aA[mf], bB[nf]);
        }
        __syncthreads();
    }

    #pragma unroll
    for (int mf = 0; mf < 4; mf++) {
        int r0 = rowBase + warpM * 64 + mf * 16 + (lane >> 2);
        int r1 = r0 + 8;
        #pragma unroll
        for (int nf = 0; nf < 8; nf++) {
            int c0 = colBase + warpN * 64 + nf * 8 + 2 * (lane & 3);
            if (r0 < M) {
                float bb = __ldg(bias + r0);
                size_t go = ((size_t)b * M + r0) * Np + c0;
                if (OUT_BF16) {
                    *(uint32_t*)((__nv_bfloat16*)outp + go) =
                        packbf2(acc[mf][nf][0] + bb, acc[mf][nf][1] + bb);
                } else {
                    float2 v = make_float2(acc[mf][nf][0] + bb, acc[mf][nf][1] + bb);
                    if (res) { float2 rr = *(const float2*)(res + go); v.x += rr.x; v.y += rr.y; }
                    *(float2*)((float*)outp + go) = v;
                }
            }
            if (r1 < M) {
                float bb = __ldg(bias + r1);
                size_t go = ((size_t)b * M + r1) * Np + c0;
                if (OUT_BF16) {
                    *(uint32_t*)((__nv_bfloat16*)outp + go) =
                        packbf2(acc[mf][nf][2] + bb, acc[mf][nf][3] + bb);
                } else {
                    float2 v = make_float2(acc[mf][nf][2] + bb, acc[mf][nf][3] + bb);
                    if (res) { float2 rr = *(const float2*)(res + go); v.x += rr.x; v.y += rr.y; }
                    *(float2*)((float*)outp + go) = v;
                }
            }
        }
    }
}

// ---------------- LayerNorm fused -> transposed bf16 [n][256] ----------------
__global__ __launch_bounds__(256) void ln_bf16_kernel(
    const float* __restrict__ in, const float* __restrict__ w,
    const float* __restrict__ bs, __nv_bfloat16* __restrict__ xh)
{
    int pos = blockIdx.x * 256 + threadIdx.x;
    int b = pos / Np, n = pos % Np;
    const float* p = in + (size_t)b * Cdim * Np + n;
    float s = 0.f, sq = 0.f;
    #pragma unroll 8
    for (int c = 0; c < Cdim; c++) { float v = p[(size_t)c * Np]; s += v; sq += v * v; }
    float mu = s * (1.f / Cdim);
    float var = fmaxf(sq * (1.f / Cdim) - mu * mu, 0.f);
    float rs = rsqrtf(var + 1e-5f);
    size_t ro = ((size_t)b * Np + n) * Cdim;
    for (int c0 = 0; c0 < Cdim; c0 += 8) {
        uint32_t ph[4];
        #pragma unroll
        for (int j = 0; j < 4; j++) {
            int c = c0 + 2 * j;
            float y0 = (p[(size_t)c * Np] - mu) * rs * w[c] + bs[c];
            float y1 = (p[(size_t)(c + 1) * Np] - mu) * rs * w[c + 1] + bs[c + 1];
            ph[j] = packbf2(y0, y1);
        }
        *(uint4*)(xh + ro + c0) = make_uint4(ph[0], ph[1], ph[2], ph[3]);
    }
}

// ---------------- transpose bf16 [C][N] -> bf16 [n][Kpad] ----------------
__global__ void tconv_kernel(const __nv_bfloat16* __restrict__ src,
                             __nv_bfloat16* __restrict__ xh, int Csrc, int Kpad)
{
    __shared__ float t[32][33];
    int c0 = blockIdx.x * 32, n0 = blockIdx.y * 32, b = blockIdx.z;
    int tx = threadIdx.x, ty = threadIdx.y;   // 32 x 8
    #pragma unroll
    for (int ii = 0; ii < 4; ii++) {
        int c = c0 + ty + ii * 8;
        float v = 0.f;
        if (c < Csrc) v = __bfloat162float(src[((size_t)b * Csrc + c) * Np + n0 + tx]);
        t[ty + ii * 8][tx] = v;
    }
    __syncthreads();
    #pragma unroll
    for (int ii = 0; ii < 4; ii++) {
        int n = n0 + ty + ii * 8;
        size_t o = ((size_t)b * Np + n) * Kpad + c0 + tx;
        xh[o] = __float2bfloat16(t[tx][ty + ii * 8]);
    }
}

// ---------------- combined weight bf16 convert ----------------
__global__ void wconv_all_kernel(
    const float* __restrict__ qkv_w, const float* __restrict__ po_w,
    const float* __restrict__ pin_w, const float* __restrict__ pout_w,
    __nv_bfloat16* __restrict__ wh)
{
    int idx = blockIdx.x * 256 + threadIdx.x;
    if (idx >= WTOT) return;
    float v;
    if (idx < WOFF_PO) {
        v = qkv_w[idx];
    } else if (idx < WOFF_PIN) {
        v = po_w[idx - WOFF_PO];
    } else if (idx < WOFF_POUT) {
        int l = idx - WOFF_PIN;              // [1408][256]
        v = (l < 1360 * 256) ? pin_w[l] : 0.f;
    } else {
        int l = idx - WOFF_POUT;             // [256][704]
        int r = l / 704, k = l % 704;
        v = (k < 680) ? pout_w[r * 680 + k] : 0.f;
    }
    wh[idx] = __float2bfloat16(v);
}

// ---------------- fused depthwise 3x3 + q/k L2-norm, vectorized 8px/thread ----------------
__global__ __launch_bounds__(256) void dwnorm_kernel(
    const __nv_bfloat16* __restrict__ in, const float* __restrict__ w,
    const float* __restrict__ bias, __nv_bfloat16* __restrict__ out,
    float* __restrict__ inv)
{
    extern __shared__ __nv_bfloat16 t[];   // Np bf16 = 32KB
    int bc = blockIdx.x;
    int c = bc % CH3, b = bc / CH3;
    const int tid = threadIdx.x;
    const uint4* ip4 = (const uint4*)(in + ((size_t)b * CH3 + c) * Np);
    uint4* t4 = (uint4*)t;
    #pragma unroll
    for (int i = 0; i < 8; i++)
        t4[i * 256 + tid] = ip4[i * 256 + tid];
    __syncthreads();

    float w00 = w[c*9+0], w01 = w[c*9+1], w02 = w[c*9+2];
    float w10 = w[c*9+3], w11 = w[c*9+4], w12 = w[c*9+5];
    float w20 = w[c*9+6], w21 = w[c*9+7], w22 = w[c*9+8];
    float bb = bias[c];
    __nv_bfloat16* op = out + ((size_t)b * CH3 + c) * Np;
    float ss = 0.f;

    #pragma unroll
    for (int it = 0; it < 8; it++) {
        int base = it * 2048 + tid * 8;
        int h = base >> 7, x0 = base & 127;
        float r0[10], r1[10], r2[10];
        load_row10(r0, t, h - 1, x0, h > 0);
        load_row10(r1, t, h,     x0, true);
        load_row10(r2, t, h + 1, x0, h < 127);
        float o[8];
        #pragma unroll
        for (int i = 0; i < 8; i++) {
            float acc = bb;
            acc += w00 * r0[i] + w01 * r0[i+1] + w02 * r0[i+2];
            acc += w10 * r1[i] + w11 * r1[i+1] + w12 * r1[i+2];
            acc += w20 * r2[i] + w21 * r2[i+1] + w22 * r2[i+2];
            o[i] = acc;
            ss += acc * acc;
        }
        uint4 pk;
        pk.x = packbf2(o[0], o[1]);
        pk.y = packbf2(o[2], o[3]);
        pk.z = packbf2(o[4], o[5]);
        pk.w = packbf2(o[6], o[7]);
        *(uint4*)(op + base) = pk;
    }

    if (c < 2 * Cdim) {
        #pragma unroll
        for (int o2 = 16; o2 > 0; o2 >>= 1) ss += __shfl_xor_sync(0xffffffffu, ss, o2);
        __shared__ float red[8];
        int wid = tid >> 5;
        if ((tid & 31) == 0) red[wid] = ss;
        __syncthreads();
        if (tid == 0) {
            float s = 0.f;
            #pragma unroll
            for (int i = 0; i < 8; i++) s += red[i];
            int which = c >> 8, cc = c & 255;
            inv[which * (Bsz * Cdim) + b * Cdim + cc] = 1.f / fmaxf(sqrtf(s), 1e-12f);
        }
    }
}

// ---------------- split-K partial S (bf16 inputs, fp32 accum) ----------------
__global__ __launch_bounds__(256) void spart_kernel(const __nv_bfloat16* __restrict__ qkv2)
{
    __shared__ float qs[HD][CHUNK + 1];
    __shared__ float ks[HD][CHUNK + 1];
    int split = blockIdx.x, h = blockIdx.y, b = blockIdx.z;
    int n0 = split * CHUNK;
    int tid = threadIdx.x;
    for (int t = tid; t < HD * CHUNK; t += 256) {
        int i = t / CHUNK, nn = t % CHUNK;
        qs[i][nn] = __bfloat162float(qkv2[((size_t)b * CH3 + h * HD + i) * Np + n0 + nn]);
        ks[i][nn] = __bfloat162float(qkv2[((size_t)b * CH3 + Cdim + h * HD + i) * Np + n0 + nn]);
    }
    __syncthreads();
    int i = tid >> 3, j0 = (tid & 7) * 4;
    float a0 = 0.f, a1 = 0.f, a2 = 0.f, a3 = 0.f;
    #pragma unroll 4
    for (int nn = 0; nn < CHUNK; nn++) {
        float qv = qs[i][nn];
        a0 += qv * ks[j0 + 0][nn];
        a1 += qv * ks[j0 + 1][nn];
        a2 += qv * ks[j0 + 2][nn];
        a3 += qv * ks[j0 + 3][nn];
    }
    size_t base = (((size_t)(b * NHEADS + h)) * SPLITS + split) * (HD * HD);
    g_spart[base + i * HD + j0 + 0] = a0;
    g_spart[base + i * HD + j0 + 1] = a1;
    g_spart[base + i * HD + j0 + 2] = a2;
    g_spart[base + i * HD + j0 + 3] = a3;
}

// ---------------- reduce partials + softmax ----------------
__global__ __launch_bounds__(1024) void attn_reduce_kernel(
    const float* __restrict__ inv, const float* __restrict__ temp)
{
    int bh = blockIdx.x;
    int b = bh / NHEADS, h = bh % NHEADS;
    int tid = threadIdx.x;
    int i = tid >> 5, j = tid & 31;
    const float* p = g_spart + (size_t)bh * SPLITS * (HD * HD) + tid;
    float s = 0.f;
    #pragma unroll 4
    for (int sp = 0; sp < SPLITS; sp++) s += p[(size_t)sp * (HD * HD)];
    s *= inv[b * Cdim + h * HD + i] * inv[Bsz * Cdim + b * Cdim + h * HD + j] * temp[h];
    float m = s;
    #pragma unroll
    for (int o = 16; o > 0; o >>= 1) m = fmaxf(m, __shfl_xor_sync(0xffffffffu, m, o));
    float e = expf(s - m);
    float sum = e;
    #pragma unroll
    for (int o = 16; o > 0; o >>= 1) sum += __shfl_xor_sync(0xffffffffu, sum, o);
    g_attn[bh * (HD * HD) + tid] = e / sum;
}

// ---------------- attn @ v -> bf16 operand [n][256] ----------------
__global__ __launch_bounds__(256) void av_bf16_kernel(
    const __nv_bfloat16* __restrict__ qkv2, __nv_bfloat16* __restrict__ xh)
{
    __shared__ float A[HD * HD];
    int h = blockIdx.y, b = blockIdx.z;
    int bh = b * NHEADS + h;
    int tid = threadIdx.x;
    #pragma unroll
    for (int t = 0; t < 4; t++) A[tid + t * 256] = g_attn[bh * (HD * HD) + tid + t * 256];
    __syncthreads();
    int n = blockIdx.x * 256 + tid;
    float vreg[HD];
    #pragma unroll
    for (int j = 0; j < HD; j++)
        vreg[j] = __bfloat162float(qkv2[((size_t)b * CH3 + 2 * Cdim + h * HD + j) * Np + n]);
    uint32_t ph[16];
    #pragma unroll
    for (int i2 = 0; i2 < 16; i2++) {
        float o0 = 0.f, o1 = 0.f;
        #pragma unroll
        for (int j = 0; j < HD; j++) {
            o0 += A[(2 * i2) * HD + j] * vreg[j];
            o1 += A[(2 * i2 + 1) * HD + j] * vreg[j];
        }
        ph[i2] = packbf2(o0, o1);
    }
    size_t o = ((size_t)b * Np + n) * Cdim + h * HD;
    #pragma unroll
    for (int q = 0; q < 4; q++)
        *(uint4*)(xh + o + q * 8) = make_uint4(ph[q*4], ph[q*4+1], ph[q*4+2], ph[q*4+3]);
}

// ---------------- tiled depthwise 3x3 + GELU gating, vectorized 8px/thread ----------------
#define GATE_SMEM (2*66*128*2)   // 33792 B
__global__ __launch_bounds__(256) void dwgate2_kernel(
    const float* __restrict__ w, const float* __restrict__ bias)
{
    extern __shared__ __nv_bfloat16 ts[];
    __nv_bfloat16* t1 = ts;               // 66*128
    __nv_bfloat16* t2 = ts + 66 * 128;
    int blk = blockIdx.x;
    int half = blk & 1;
    int c = (blk >> 1) % HID;
    int b = blk / (2 * HID);
    int h0 = half * 64;
    int tid = threadIdx.x;

    const uint4* s1 = (const uint4*)(g_pin + ((size_t)b * HID2 + c) * Np);
    const uint4* s2 = (const uint4*)(g_pin + ((size_t)b * HID2 + c + HID) * Np);
    uint4* t14 = (uint4*)t1;
    uint4* t24 = (uint4*)t2;
    const uint4 z4 = make_uint4(0u, 0u, 0u, 0u);
    for (int i = tid; i < 66 * 16; i += 256) {
        int r = i >> 4, q = i & 15;
        int grow = h0 - 1 + r;
        bool ok = (grow >= 0) && (grow < Hh);
        t14[i] = ok ? s1[grow * 16 + q] : z4;
        t24[i] = ok ? s2[grow * 16 + q] : z4;
    }
    __syncthreads();

    float a00 = w[c*9+0], a01 = w[c*9+1], a02 = w[c*9+2];
    float a10 = w[c*9+3], a11 = w[c*9+4], a12 = w[c*9+5];
    float a20 = w[c*9+6], a21 = w[c*9+7], a22 = w[c*9+8];
    int c2 = c + HID;
    float b00 = w[c2*9+0], b01 = w[c2*9+1], b02 = w[c2*9+2];
    float b10 = w[c2*9+3], b11 = w[c2*9+4], b12 = w[c2*9+5];
    float b20 = w[c2*9+6], b21 = w[c2*9+7], b22 = w[c2*9+8];
    float ba = bias[c], bg = bias[c2];

    __nv_bfloat16* op = g_gate + ((size_t)b * HID + c) * Np + h0 * Wd;
    #pragma unroll
    for (int it = 0; it < 4; it++) {
        int base = it * 2048 + tid * 8;
        int h = base >> 7, x0 = base & 127;
        float p0[10], p1[10], p2[10];
        float q0[10], q1[10], q2[10];
        load_row10(p0, t1, h,     x0, true);
        load_row10(p1, t1, h + 1, x0, true);
        load_row10(p2, t1, h + 2, x0, true);
        load_row10(q0, t2, h,     x0, true);
        load_row10(q1, t2, h + 1, x0, true);
        load_row10(q2, t2, h + 2, x0, true);
        float o[8];
        #pragma unroll
        for (int i = 0; i < 8; i++) {
            float a = ba, g = bg;
            a += a00 * p0[i] + a01 * p0[i+1] + a02 * p0[i+2];
            a += a10 * p1[i] + a11 * p1[i+1] + a12 * p1[i+2];
            a += a20 * p2[i] + a21 * p2[i+1] + a22 * p2[i+2];
            g += b00 * q0[i] + b01 * q0[i+1] + b02 * q0[i+2];
            g += b10 * q1[i] + b11 * q1[i+1] + b12 * q1[i+2];
            g += b20 * q2[i] + b21 * q2[i+1] + b22 * q2[i+2];
            float gelu = 0.5f * g * (1.f + erff(g * 0.70710678118654752f));
            o[i] = a * gelu;
        }
        uint4 pk;
        pk.x = packbf2(o[0], o[1]);
        pk.y = packbf2(o[2], o[3]);
        pk.z = packbf2(o[4], o[5]);
        pk.w = packbf2(o[6], o[7]);
        *(uint4*)(op + base) = pk;
    }
}

// ---------------- launcher ----------------
extern "C" void kernel_launch(void* const* d_in, const int* in_sizes, int n_in,
                              void* d_out, int out_size)
{
    const float* x        = (const float*)d_in[0];
    const float* n1_w     = (const float*)d_in[1];
    const float* n1_b     = (const float*)d_in[2];
    const float* temp     = (const float*)d_in[3];
    const float* qkv_w    = (const float*)d_in[4];
    const float* qkv_b    = (const float*)d_in[5];
    const float* qkv_dw_w = (const float*)d_in[6];
    const float* qkv_dw_b = (const float*)d_in[7];
    const float* po_w     = (const float*)d_in[8];
    const float* po_b     = (const float*)d_in[9];
    const float* n2_w     = (const float*)d_in[10];
    const float* n2_b     = (const float*)d_in[11];
    const float* pin_w    = (const float*)d_in[12];
    const float* pin_b    = (const float*)d_in[13];
    const float* dw_w     = (const float*)d_in[14];
    const float* dw_b     = (const float*)d_in[15];
    const float* pout_w   = (const float*)d_in[16];
    const float* pout_b   = (const float*)d_in[17];
    float* out = (float*)d_out;

    float *p_inv, *p_x1;
    __nv_bfloat16 *p_qkv, *p_qkv2, *p_pin, *p_gate, *p_xh, *p_wh;
    cudaGetSymbolAddress((void**)&p_qkv,  g_qkv);
    cudaGetSymbolAddress((void**)&p_qkv2, g_qkv2);
    cudaGetSymbolAddress((void**)&p_inv,  g_inv);
    cudaGetSymbolAddress((void**)&p_x1,   g_x1);
    cudaGetSymbolAddress((void**)&p_pin,  g_pin);
    cudaGetSymbolAddress((void**)&p_gate, g_gate);
    cudaGetSymbolAddress((void**)&p_xh,   g_xh);
    cudaGetSymbolAddress((void**)&p_wh,   g_wh);

    cudaFuncSetAttribute(gemm_mma_kernel<true>,  cudaFuncAttributeMaxDynamicSharedMemorySize, GEMM_SMEM);
    cudaFuncSetAttribute(gemm_mma_kernel<false>, cudaFuncAttributeMaxDynamicSharedMemorySize, GEMM_SMEM);
    cudaFuncSetAttribute(dwnorm_kernel,  cudaFuncAttributeMaxDynamicSharedMemorySize, Np * 2);
    cudaFuncSetAttribute(dwgate2_kernel, cudaFuncAttributeMaxDynamicSharedMemorySize, GATE_SMEM);

    // 0) weight conversion
    wconv_all_kernel<<<(WTOT + 255) / 256, 256>>>(qkv_w, po_w, pin_w, pout_w, p_wh);

    // 1) LN1 -> bf16 operand
    ln_bf16_kernel<<<Bsz*Np/256, 256>>>(x, n1_w, n1_b, p_xh);
    // 2) qkv GEMM (M=768, K=256) -> bf16
    gemm_mma_kernel<true><<<dim3(Np/256, 6, Bsz), 256, GEMM_SMEM>>>(
        p_wh + WOFF_QKV, p_xh, qkv_b, nullptr, p_qkv, CH3, 256);
    // 3) depthwise 3x3 on qkv, fused q/k norms
    dwnorm_kernel<<<Bsz*CH3, 256, Np*2>>>(p_qkv, qkv_dw_w, qkv_dw_b, p_qkv2, p_inv);
    // 4) split-K partial S
    spart_kernel<<<dim3(SPLITS, NHEADS, Bsz), 256>>>(p_qkv2);
    // 5) reduce + softmax
    attn_reduce_kernel<<<Bsz*NHEADS, 1024>>>(p_inv, temp);
    // 6) attn @ v -> bf16 operand
    av_bf16_kernel<<<dim3(Np/256, NHEADS, Bsz), 256>>>(p_qkv2, p_xh);
    // 7) po GEMM + residual -> x1 (fp32)
    gemm_mma_kernel<false><<<dim3(Np/256, 2, Bsz), 256, GEMM_SMEM>>>(
        p_wh + WOFF_PO, p_xh, po_b, x, p_x1, Cdim, 256);
    // 8) LN2 -> bf16 operand
    ln_bf16_kernel<<<Bsz*Np/256, 256>>>(p_x1, n2_w, n2_b, p_xh);
    // 9) FFN project-in (M=1360, pad 1408) -> bf16
    gemm_mma_kernel<true><<<dim3(Np/256, MPAD_PIN/128, Bsz), 256, GEMM_SMEM>>>(
        p_wh + WOFF_PIN, p_xh, pin_b, nullptr, p_pin, HID2, 256);
    // 10) tiled depthwise + GELU gate (bf16)
    dwgate2_kernel<<<Bsz*HID*2, 256, GATE_SMEM>>>(dw_w, dw_b);
    // 11) transpose gate -> operand (K=680 -> 704)
    tconv_kernel<<<dim3(KPAD_G/32, Np/32, Bsz), dim3(32, 8)>>>(p_gate, p_xh, HID, KPAD_G);
    // 12) pout GEMM + residual -> out (fp32)
    gemm_mma_kernel<false><<<dim3(Np/256, 2, Bsz), 256, GEMM_SMEM>>>(
        p_wh + WOFF_POUT, p_xh, pout_b, p_x1, out, Cdim, KPAD_G);
}

// round 9
// speedup vs baseline: 1.1138x; 1.1138x over previous
#include <cuda_runtime.h>
#include <cuda_bf16.h>
#include <math.h>
#include <stdint.h>

// ---------------- problem constants ----------------
#define Bsz    4
#define Cdim   256
#define Hh     128
#define Wd     128
#define Np     (Hh*Wd)        // 16384
#define CH3    (3*Cdim)       // 768
#define HID    680
#define HID2   1360
#define NHEADS 8
#define HD     32
#define SPLITS 128
#define CHUNK  (Np/SPLITS)    // 128

#define KPAD_G 704
#define MPAD_PIN 1408

// ---------------- scratch (device globals; no runtime alloc) ----------------
__device__ __align__(16) __nv_bfloat16 g_qkv [(size_t)Bsz*CH3 *Np];
__device__ __align__(16) __nv_bfloat16 g_qkv2[(size_t)Bsz*CH3 *Np];
__device__ float g_inv  [2*Bsz*Cdim];
__device__ float g_spart[(size_t)Bsz*NHEADS*SPLITS*HD*HD];
__device__ float g_attn [Bsz*NHEADS*HD*HD];
__device__ float g_x1   [(size_t)Bsz*Cdim*Np];
__device__ __align__(16) __nv_bfloat16 g_pin [(size_t)Bsz*HID2*Np];
__device__ __align__(16) __nv_bfloat16 g_gate[(size_t)Bsz*HID *Np];

// bf16 operand buffer (X, [b][n][K])
__device__ __align__(16) __nv_bfloat16 g_xh[(size_t)Bsz*Np*KPAD_G];
// weights: qkv(768*256) | po(256*256) | pin(1408*256) | pout(256*704)
#define WOFF_QKV  0
#define WOFF_PO   (768*256)
#define WOFF_PIN  (WOFF_PO + 256*256)
#define WOFF_POUT (WOFF_PIN + 1408*256)
#define WTOT      (WOFF_POUT + 256*704)
__device__ __align__(16) __nv_bfloat16 g_wh[WTOT];

// ---------------- PTX helpers ----------------
__device__ __forceinline__ uint32_t smem_u32(const void* p) {
    uint32_t a;
    asm("{ .reg .u64 t; cvta.to.shared.u64 t, %1; cvt.u32.u64 %0, t; }" : "=r"(a) : "l"(p));
    return a;
}
#define CP_ASYNC16(dst, src) \
    asm volatile("cp.async.cg.shared.global [%0], [%1], 16;" :: "r"(dst), "l"(src) : "memory")
#define CP_COMMIT() asm volatile("cp.async.commit_group;" ::: "memory")
#define CP_WAIT(n)  asm volatile("cp.async.wait_group %0;" :: "n"(n) : "memory")

__device__ __forceinline__ void ldsm4(uint32_t* r, uint32_t addr) {
    asm volatile("ldmatrix.sync.aligned.m8n8.x4.shared.b16 {%0,%1,%2,%3}, [%4];"
                 : "=r"(r[0]), "=r"(r[1]), "=r"(r[2]), "=r"(r[3]) : "r"(addr));
}
__device__ __forceinline__ void mma16816(float* c, const uint32_t* a, const uint32_t* b) {
    asm volatile(
        "mma.sync.aligned.m16n8k16.row.col.f32.bf16.bf16.f32 "
        "{%0,%1,%2,%3}, {%4,%5,%6,%7}, {%8,%9}, {%0,%1,%2,%3};"
        : "+f"(c[0]), "+f"(c[1]), "+f"(c[2]), "+f"(c[3])
        : "r"(a[0]), "r"(a[1]), "r"(a[2]), "r"(a[3]), "r"(b[0]), "r"(b[1]));
}
__device__ __forceinline__ uint32_t packbf2(float a, float b) {
    __nv_bfloat162 h = __floats2bfloat162_rn(a, b);
    return *(uint32_t*)&h;
}
__device__ __forceinline__ void unpack8(const uint4 v, float* r) {
    float2 f;
    f = __bfloat1622float2(*(const __nv_bfloat162*)&v.x); r[0] = f.x; r[1] = f.y;
    f = __bfloat1622float2(*(const __nv_bfloat162*)&v.y); r[2] = f.x; r[3] = f.y;
    f = __bfloat1622float2(*(const __nv_bfloat162*)&v.z); r[4] = f.x; r[5] = f.y;
    f = __bfloat1622float2(*(const __nv_bfloat162*)&v.w); r[6] = f.x; r[7] = f.y;
}
__device__ __forceinline__ void load_row10(float* r, const __nv_bfloat16* t,
                                           int row, int x0, bool valid) {
    if (!valid) {
        #pragma unroll
        for (int i = 0; i < 10; i++) r[i] = 0.f;
        return;
    }
    const __nv_bfloat16* p = t + row * 128;
    uint4 v = *(const uint4*)(p + x0);
    unpack8(v, r + 1);
    r[0] = (x0 > 0)   ? __bfloat162float(p[x0 - 1]) : 0.f;
    r[9] = (x0 < 120) ? __bfloat162float(p[x0 + 8]) : 0.f;
}

// ================= mma.sync GEMM bf16 (exact R6 config: 128x128, BK=32, 3-stage) =================
#define TARR_B   10240          // 128 rows x 80 B (32 bf16 + 8 pad)
#define STAGE_B  (2*TARR_B)     // W, X
#define GEMM_SMEM (3*STAGE_B)   // 61440

__device__ __forceinline__ void gemm_issue_tile(
    uint32_t st, int tid, const __nv_bfloat16* Wh, const __nv_bfloat16* Xh_b,
    int rowBase, int Kpad, int k0)
{
    #pragma unroll
    for (int c = tid; c < 512; c += 256) {
        int r = c >> 2, cc = c & 3;
        uint32_t so = st + r * 80 + cc * 16;
        size_t wo = (size_t)(rowBase + r) * Kpad + k0 + cc * 8;
        size_t xo = (size_t)r * Kpad + k0 + cc * 8;
        CP_ASYNC16(so,          Wh + wo);
        CP_ASYNC16(so + TARR_B, Xh_b + xo);
    }
    CP_COMMIT();
}

template<bool OUT_BF16>
__global__ __launch_bounds__(256) void gemm_mma_kernel(
    const __nv_bfloat16* __restrict__ Wh,
    const __nv_bfloat16* __restrict__ Xh,
    const float* __restrict__ bias, const float* __restrict__ res,
    void* __restrict__ outp, int M, int Kpad)
{
    extern __shared__ char smem[];
    const uint32_t sb = smem_u32(smem);
    const int tid = threadIdx.x, lane = tid & 31, wid = tid >> 5;
    const int warpM = wid & 1, warpN = wid >> 1;
    const int rowBase = blockIdx.y * 128, colBase = blockIdx.x * 128, b = blockIdx.z;

    const __nv_bfloat16* Xh_b = Xh + ((size_t)b * Np + colBase) * Kpad;

    float acc[4][4][4];
    #pragma unroll
    for (int i = 0; i < 4; i++)
        #pragma unroll
        for (int j = 0; j < 4; j++)
            #pragma unroll
            for (int k = 0; k < 4; k++) acc[i][j][k] = 0.f;

    const int nk = Kpad >> 5;
    gemm_issue_tile(sb,           tid, Wh, Xh_b, rowBase, Kpad, 0);
    gemm_issue_tile(sb + STAGE_B, tid, Wh, Xh_b, rowBase, Kpad, 32);

    for (int i = 0; i < nk; i++) {
        if (i + 2 < nk) {
            gemm_issue_tile(sb + ((i + 2) % 3) * STAGE_B, tid, Wh, Xh_b,
                            rowBase, Kpad, (i + 2) << 5);
            CP_WAIT(2);
        } else if (i + 1 < nk) {
            CP_WAIT(1);
        } else {
            CP_WAIT(0);
        }
        __syncthreads();

        const uint32_t st = sb + (i % 3) * STAGE_B;
        #pragma unroll
        for (int kk = 0; kk < 2; kk++) {
            uint32_t aA[4][4], bB[4][2];
            const int arow = lane & 15, ahalf = lane >> 4;
            #pragma unroll
            for (int mf = 0; mf < 4; mf++) {
                uint32_t ad = st + (uint32_t)(warpM * 64 + mf * 16 + arow) * 80
                              + kk * 32 + ahalf * 16;
                ldsm4(aA[mf], ad);
            }
            #pragma unroll
            for (int nfp = 0; nfp < 2; nfp++) {
                int nrow = warpN * 32 + nfp * 16 + ((lane >> 4) * 8 + (lane & 7));
                int kb = (lane >> 3) & 1;
                uint32_t bd = st + TARR_B + (uint32_t)nrow * 80 + kk * 32 + kb * 16;
                uint32_t t[4];
                ldsm4(t, bd);
                bB[nfp*2][0] = t[0]; bB[nfp*2][1] = t[1];
                bB[nfp*2+1][0] = t[2]; bB[nfp*2+1][1] = t[3];
            }
            #pragma unroll
            for (int mf = 0; mf < 4; mf++)
                #pragma unroll
                for (int nf = 0; nf < 4; nf++)
                    mma16816(acc[mf][nf], aA[mf], bB[nf]);
        }
        __syncthreads();
    }

    #pragma unroll
    for (int mf = 0; mf < 4; mf++) {
        int r0 = rowBase + warpM * 64 + mf * 16 + (lane >> 2);
        int r1 = r0 + 8;
        #pragma unroll
        for (int nf = 0; nf < 4; nf++) {
            int c0 = colBase + warpN * 32 + nf * 8 + 2 * (lane & 3);
            if (r0 < M) {
                float bb = __ldg(bias + r0);
                size_t go = ((size_t)b * M + r0) * Np + c0;
                if (OUT_BF16) {
                    *(uint32_t*)((__nv_bfloat16*)outp + go) =
                        packbf2(acc[mf][nf][0] + bb, acc[mf][nf][1] + bb);
                } else {
                    float2 v = make_float2(acc[mf][nf][0] + bb, acc[mf][nf][1] + bb);
                    if (res) { float2 rr = *(const float2*)(res + go); v.x += rr.x; v.y += rr.y; }
                    *(float2*)((float*)outp + go) = v;
                }
            }
            if (r1 < M) {
                float bb = __ldg(bias + r1);
                size_t go = ((size_t)b * M + r1) * Np + c0;
                if (OUT_BF16) {
                    *(uint32_t*)((__nv_bfloat16*)outp + go) =
                        packbf2(acc[mf][nf][2] + bb, acc[mf][nf][3] + bb);
                } else {
                    float2 v = make_float2(acc[mf][nf][2] + bb, acc[mf][nf][3] + bb);
                    if (res) { float2 rr = *(const float2*)(res + go); v.x += rr.x; v.y += rr.y; }
                    *(float2*)((float*)outp + go) = v;
                }
            }
        }
    }
}

// ---------------- LayerNorm fused -> transposed bf16 [n][256] ----------------
__global__ __launch_bounds__(256) void ln_bf16_kernel(
    const float* __restrict__ in, const float* __restrict__ w,
    const float* __restrict__ bs, __nv_bfloat16* __restrict__ xh)
{
    int pos = blockIdx.x * 256 + threadIdx.x;
    int b = pos / Np, n = pos % Np;
    const float* p = in + (size_t)b * Cdim * Np + n;
    float s = 0.f, sq = 0.f;
    #pragma unroll 8
    for (int c = 0; c < Cdim; c++) { float v = p[(size_t)c * Np]; s += v; sq += v * v; }
    float mu = s * (1.f / Cdim);
    float var = fmaxf(sq * (1.f / Cdim) - mu * mu, 0.f);
    float rs = rsqrtf(var + 1e-5f);
    size_t ro = ((size_t)b * Np + n) * Cdim;
    for (int c0 = 0; c0 < Cdim; c0 += 8) {
        uint32_t ph[4];
        #pragma unroll
        for (int j = 0; j < 4; j++) {
            int c = c0 + 2 * j;
            float y0 = (p[(size_t)c * Np] - mu) * rs * w[c] + bs[c];
            float y1 = (p[(size_t)(c + 1) * Np] - mu) * rs * w[c + 1] + bs[c + 1];
            ph[j] = packbf2(y0, y1);
        }
        *(uint4*)(xh + ro + c0) = make_uint4(ph[0], ph[1], ph[2], ph[3]);
    }
}

// ---------------- transpose bf16 [C][N] -> bf16 [n][Kpad] ----------------
__global__ void tconv_kernel(const __nv_bfloat16* __restrict__ src,
                             __nv_bfloat16* __restrict__ xh, int Csrc, int Kpad)
{
    __shared__ float t[32][33];
    int c0 = blockIdx.x * 32, n0 = blockIdx.y * 32, b = blockIdx.z;
    int tx = threadIdx.x, ty = threadIdx.y;   // 32 x 8
    #pragma unroll
    for (int ii = 0; ii < 4; ii++) {
        int c = c0 + ty + ii * 8;
        float v = 0.f;
        if (c < Csrc) v = __bfloat162float(src[((size_t)b * Csrc + c) * Np + n0 + tx]);
        t[ty + ii * 8][tx] = v;
    }
    __syncthreads();
    #pragma unroll
    for (int ii = 0; ii < 4; ii++) {
        int n = n0 + ty + ii * 8;
        size_t o = ((size_t)b * Np + n) * Kpad + c0 + tx;
        xh[o] = __float2bfloat16(t[tx][ty + ii * 8]);
    }
}

// ---------------- combined weight bf16 convert ----------------
__global__ void wconv_all_kernel(
    const float* __restrict__ qkv_w, const float* __restrict__ po_w,
    const float* __restrict__ pin_w, const float* __restrict__ pout_w,
    __nv_bfloat16* __restrict__ wh)
{
    int idx = blockIdx.x * 256 + threadIdx.x;
    if (idx >= WTOT) return;
    float v;
    if (idx < WOFF_PO) {
        v = qkv_w[idx];
    } else if (idx < WOFF_PIN) {
        v = po_w[idx - WOFF_PO];
    } else if (idx < WOFF_POUT) {
        int l = idx - WOFF_PIN;              // [1408][256]
        v = (l < 1360 * 256) ? pin_w[l] : 0.f;
    } else {
        int l = idx - WOFF_POUT;             // [256][704]
        int r = l / 704, k = l % 704;
        v = (k < 680) ? pout_w[r * 680 + k] : 0.f;
    }
    wh[idx] = __float2bfloat16(v);
}

// ---------------- fused depthwise 3x3 + q/k L2-norm, vectorized 8px/thread ----------------
__global__ __launch_bounds__(256) void dwnorm_kernel(
    const __nv_bfloat16* __restrict__ in, const float* __restrict__ w,
    const float* __restrict__ bias, __nv_bfloat16* __restrict__ out,
    float* __restrict__ inv)
{
    extern __shared__ __nv_bfloat16 t[];   // Np bf16 = 32KB
    int bc = blockIdx.x;
    int c = bc % CH3, b = bc / CH3;
    const int tid = threadIdx.x;
    const uint4* ip4 = (const uint4*)(in + ((size_t)b * CH3 + c) * Np);
    uint4* t4 = (uint4*)t;
    #pragma unroll
    for (int i = 0; i < 8; i++)
        t4[i * 256 + tid] = ip4[i * 256 + tid];
    __syncthreads();

    float w00 = w[c*9+0], w01 = w[c*9+1], w02 = w[c*9+2];
    float w10 = w[c*9+3], w11 = w[c*9+4], w12 = w[c*9+5];
    float w20 = w[c*9+6], w21 = w[c*9+7], w22 = w[c*9+8];
    float bb = bias[c];
    __nv_bfloat16* op = out + ((size_t)b * CH3 + c) * Np;
    float ss = 0.f;

    #pragma unroll
    for (int it = 0; it < 8; it++) {
        int base = it * 2048 + tid * 8;
        int h = base >> 7, x0 = base & 127;
        float r0[10], r1[10], r2[10];
        load_row10(r0, t, h - 1, x0, h > 0);
        load_row10(r1, t, h,     x0, true);
        load_row10(r2, t, h + 1, x0, h < 127);
        float o[8];
        #pragma unroll
        for (int i = 0; i < 8; i++) {
            float acc = bb;
            acc += w00 * r0[i] + w01 * r0[i+1] + w02 * r0[i+2];
            acc += w10 * r1[i] + w11 * r1[i+1] + w12 * r1[i+2];
            acc += w20 * r2[i] + w21 * r2[i+1] + w22 * r2[i+2];
            o[i] = acc;
            ss += acc * acc;
        }
        uint4 pk;
        pk.x = packbf2(o[0], o[1]);
        pk.y = packbf2(o[2], o[3]);
        pk.z = packbf2(o[4], o[5]);
        pk.w = packbf2(o[6], o[7]);
        *(uint4*)(op + base) = pk;
    }

    if (c < 2 * Cdim) {
        #pragma unroll
        for (int o2 = 16; o2 > 0; o2 >>= 1) ss += __shfl_xor_sync(0xffffffffu, ss, o2);
        __shared__ float red[8];
        int wid = tid >> 5;
        if ((tid & 31) == 0) red[wid] = ss;
        __syncthreads();
        if (tid == 0) {
            float s = 0.f;
            #pragma unroll
            for (int i = 0; i < 8; i++) s += red[i];
            int which = c >> 8, cc = c & 255;
            inv[which * (Bsz * Cdim) + b * Cdim + cc] = 1.f / fmaxf(sqrtf(s), 1e-12f);
        }
    }
}

// ---------------- split-K partial S (bf16 inputs, fp32 accum) ----------------
__global__ __launch_bounds__(256) void spart_kernel(const __nv_bfloat16* __restrict__ qkv2)
{
    __shared__ float qs[HD][CHUNK + 1];
    __shared__ float ks[HD][CHUNK + 1];
    int split = blockIdx.x, h = blockIdx.y, b = blockIdx.z;
    int n0 = split * CHUNK;
    int tid = threadIdx.x;
    for (int t = tid; t < HD * CHUNK; t += 256) {
        int i = t / CHUNK, nn = t % CHUNK;
        qs[i][nn] = __bfloat162float(qkv2[((size_t)b * CH3 + h * HD + i) * Np + n0 + nn]);
        ks[i][nn] = __bfloat162float(qkv2[((size_t)b * CH3 + Cdim + h * HD + i) * Np + n0 + nn]);
    }
    __syncthreads();
    int i = tid >> 3, j0 = (tid & 7) * 4;
    float a0 = 0.f, a1 = 0.f, a2 = 0.f, a3 = 0.f;
    #pragma unroll 4
    for (int nn = 0; nn < CHUNK; nn++) {
        float qv = qs[i][nn];
        a0 += qv * ks[j0 + 0][nn];
        a1 += qv * ks[j0 + 1][nn];
        a2 += qv * ks[j0 + 2][nn];
        a3 += qv * ks[j0 + 3][nn];
    }
    size_t base = (((size_t)(b * NHEADS + h)) * SPLITS + split) * (HD * HD);
    g_spart[base + i * HD + j0 + 0] = a0;
    g_spart[base + i * HD + j0 + 1] = a1;
    g_spart[base + i * HD + j0 + 2] = a2;
    g_spart[base + i * HD + j0 + 3] = a3;
}

// ---------------- reduce partials + softmax ----------------
__global__ __launch_bounds__(1024) void attn_reduce_kernel(
    const float* __restrict__ inv, const float* __restrict__ temp)
{
    int bh = blockIdx.x;
    int b = bh / NHEADS, h = bh % NHEADS;
    int tid = threadIdx.x;
    int i = tid >> 5, j = tid & 31;
    const float* p = g_spart + (size_t)bh * SPLITS * (HD * HD) + tid;
    float s = 0.f;
    #pragma unroll 4
    for (int sp = 0; sp < SPLITS; sp++) s += p[(size_t)sp * (HD * HD)];
    s *= inv[b * Cdim + h * HD + i] * inv[Bsz * Cdim + b * Cdim + h * HD + j] * temp[h];
    float m = s;
    #pragma unroll
    for (int o = 16; o > 0; o >>= 1) m = fmaxf(m, __shfl_xor_sync(0xffffffffu, m, o));
    float e = expf(s - m);
    float sum = e;
    #pragma unroll
    for (int o = 16; o > 0; o >>= 1) sum += __shfl_xor_sync(0xffffffffu, sum, o);
    g_attn[bh * (HD * HD) + tid] = e / sum;
}

// ---------------- attn @ v -> bf16 operand [n][256], 2 pixels per thread ----------------
__global__ __launch_bounds__(256) void av_bf16_kernel(
    const __nv_bfloat16* __restrict__ qkv2, __nv_bfloat16* __restrict__ xh)
{
    __shared__ float A[HD * HD];
    int h = blockIdx.y, b = blockIdx.z;
    int bh = b * NHEADS + h;
    int tid = threadIdx.x;
    #pragma unroll
    for (int t = 0; t < 4; t++) A[tid + t * 256] = g_attn[bh * (HD * HD) + tid + t * 256];
    __syncthreads();
    int n0 = blockIdx.x * 512 + tid * 2;       // two adjacent pixels
    float2 vf[HD];
    #pragma unroll
    for (int j = 0; j < HD; j++) {
        __nv_bfloat162 v2 = *(const __nv_bfloat162*)(
            qkv2 + ((size_t)b * CH3 + 2 * Cdim + h * HD + j) * Np + n0);
        vf[j] = __bfloat1622float2(v2);
    }
    float o0[HD], o1[HD];
    #pragma unroll
    for (int i = 0; i < HD; i++) {
        float s0 = 0.f, s1 = 0.f;
        #pragma unroll
        for (int j = 0; j < HD; j++) {
            float a = A[i * HD + j];
            s0 += a * vf[j].x;
            s1 += a * vf[j].y;
        }
        o0[i] = s0; o1[i] = s1;
    }
    size_t ob = ((size_t)b * Np + n0) * Cdim + h * HD;
    #pragma unroll
    for (int q = 0; q < 4; q++) {
        uint4 pk0, pk1;
        pk0.x = packbf2(o0[q*8+0], o0[q*8+1]); pk0.y = packbf2(o0[q*8+2], o0[q*8+3]);
        pk0.z = packbf2(o0[q*8+4], o0[q*8+5]); pk0.w = packbf2(o0[q*8+6], o0[q*8+7]);
        pk1.x = packbf2(o1[q*8+0], o1[q*8+1]); pk1.y = packbf2(o1[q*8+2], o1[q*8+3]);
        pk1.z = packbf2(o1[q*8+4], o1[q*8+5]); pk1.w = packbf2(o1[q*8+6], o1[q*8+7]);
        *(uint4*)(xh + ob + q * 8)        = pk0;
        *(uint4*)(xh + ob + Cdim + q * 8) = pk1;
    }
}

// ---------------- tiled depthwise 3x3 + GELU gating, vectorized 8px/thread ----------------
#define GATE_SMEM (2*66*128*2)   // 33792 B
__global__ __launch_bounds__(256) void dwgate2_kernel(
    const float* __restrict__ w, const float* __restrict__ bias)
{
    extern __shared__ __nv_bfloat16 ts[];
    __nv_bfloat16* t1 = ts;               // 66*128
    __nv_bfloat16* t2 = ts + 66 * 128;
    int blk = blockIdx.x;
    int half = blk & 1;
    int c = (blk >> 1) % HID;
    int b = blk / (2 * HID);
    int h0 = half * 64;
    int tid = threadIdx.x;

    const uint4* s1 = (const uint4*)(g_pin + ((size_t)b * HID2 + c) * Np);
    const uint4* s2 = (const uint4*)(g_pin + ((size_t)b * HID2 + c + HID) * Np);
    uint4* t14 = (uint4*)t1;
    uint4* t24 = (uint4*)t2;
    const uint4 z4 = make_uint4(0u, 0u, 0u, 0u);
    for (int i = tid; i < 66 * 16; i += 256) {
        int r = i >> 4, q = i & 15;
        int grow = h0 - 1 + r;
        bool ok = (grow >= 0) && (grow < Hh);
        t14[i] = ok ? s1[grow * 16 + q] : z4;
        t24[i] = ok ? s2[grow * 16 + q] : z4;
    }
    __syncthreads();

    float a00 = w[c*9+0], a01 = w[c*9+1], a02 = w[c*9+2];
    float a10 = w[c*9+3], a11 = w[c*9+4], a12 = w[c*9+5];
    float a20 = w[c*9+6], a21 = w[c*9+7], a22 = w[c*9+8];
    int c2 = c + HID;
    float b00 = w[c2*9+0], b01 = w[c2*9+1], b02 = w[c2*9+2];
    float b10 = w[c2*9+3], b11 = w[c2*9+4], b12 = w[c2*9+5];
    float b20 = w[c2*9+6], b21 = w[c2*9+7], b22 = w[c2*9+8];
    float ba = bias[c], bg = bias[c2];

    __nv_bfloat16* op = g_gate + ((size_t)b * HID + c) * Np + h0 * Wd;
    #pragma unroll
    for (int it = 0; it < 4; it++) {
        int base = it * 2048 + tid * 8;
        int h = base >> 7, x0 = base & 127;
        float p0[10], p1[10], p2[10];
        float q0[10], q1[10], q2[10];
        load_row10(p0, t1, h,     x0, true);
        load_row10(p1, t1, h + 1, x0, true);
        load_row10(p2, t1, h + 2, x0, true);
        load_row10(q0, t2, h,     x0, true);
        load_row10(q1, t2, h + 1, x0, true);
        load_row10(q2, t2, h + 2, x0, true);
        float o[8];
        #pragma unroll
        for (int i = 0; i < 8; i++) {
            float a = ba, g = bg;
            a += a00 * p0[i] + a01 * p0[i+1] + a02 * p0[i+2];
            a += a10 * p1[i] + a11 * p1[i+1] + a12 * p1[i+2];
            a += a20 * p2[i] + a21 * p2[i+1] + a22 * p2[i+2];
            g += b00 * q0[i] + b01 * q0[i+1] + b02 * q0[i+2];
            g += b10 * q1[i] + b11 * q1[i+1] + b12 * q1[i+2];
            g += b20 * q2[i] + b21 * q2[i+1] + b22 * q2[i+2];
            float gelu = 0.5f * g * (1.f + erff(g * 0.70710678118654752f));
            o[i] = a * gelu;
        }
        uint4 pk;
        pk.x = packbf2(o[0], o[1]);
        pk.y = packbf2(o[2], o[3]);
        pk.z = packbf2(o[4], o[5]);
        pk.w = packbf2(o[6], o[7]);
        *(uint4*)(op + base) = pk;
    }
}

// ---------------- launcher ----------------
extern "C" void kernel_launch(void* const* d_in, const int* in_sizes, int n_in,
                              void* d_out, int out_size)
{
    const float* x        = (const float*)d_in[0];
    const float* n1_w     = (const float*)d_in[1];
    const float* n1_b     = (const float*)d_in[2];
    const float* temp     = (const float*)d_in[3];
    const float* qkv_w    = (const float*)d_in[4];
    const float* qkv_b    = (const float*)d_in[5];
    const float* qkv_dw_w = (const float*)d_in[6];
    const float* qkv_dw_b = (const float*)d_in[7];
    const float* po_w     = (const float*)d_in[8];
    const float* po_b     = (const float*)d_in[9];
    const float* n2_w     = (const float*)d_in[10];
    const float* n2_b     = (const float*)d_in[11];
    const float* pin_w    = (const float*)d_in[12];
    const float* pin_b    = (const float*)d_in[13];
    const float* dw_w     = (const float*)d_in[14];
    const float* dw_b     = (const float*)d_in[15];
    const float* pout_w   = (const float*)d_in[16];
    const float* pout_b   = (const float*)d_in[17];
    float* out = (float*)d_out;

    float *p_inv, *p_x1;
    __nv_bfloat16 *p_qkv, *p_qkv2, *p_pin, *p_gate, *p_xh, *p_wh;
    cudaGetSymbolAddress((void**)&p_qkv,  g_qkv);
    cudaGetSymbolAddress((void**)&p_qkv2, g_qkv2);
    cudaGetSymbolAddress((void**)&p_inv,  g_inv);
    cudaGetSymbolAddress((void**)&p_x1,   g_x1);
    cudaGetSymbolAddress((void**)&p_pin,  g_pin);
    cudaGetSymbolAddress((void**)&p_gate, g_gate);
    cudaGetSymbolAddress((void**)&p_xh,   g_xh);
    cudaGetSymbolAddress((void**)&p_wh,   g_wh);

    cudaFuncSetAttribute(gemm_mma_kernel<true>,  cudaFuncAttributeMaxDynamicSharedMemorySize, GEMM_SMEM);
    cudaFuncSetAttribute(gemm_mma_kernel<false>, cudaFuncAttributeMaxDynamicSharedMemorySize, GEMM_SMEM);
    cudaFuncSetAttribute(dwnorm_kernel,  cudaFuncAttributeMaxDynamicSharedMemorySize, Np * 2);
    cudaFuncSetAttribute(dwgate2_kernel, cudaFuncAttributeMaxDynamicSharedMemorySize, GATE_SMEM);

    // 0) weight conversion
    wconv_all_kernel<<<(WTOT + 255) / 256, 256>>>(qkv_w, po_w, pin_w, pout_w, p_wh);

    // 1) LN1 -> bf16 operand
    ln_bf16_kernel<<<Bsz*Np/256, 256>>>(x, n1_w, n1_b, p_xh);
    // 2) qkv GEMM (M=768, K=256) -> bf16
    gemm_mma_kernel<true><<<dim3(Np/128, 6, Bsz), 256, GEMM_SMEM>>>(
        p_wh + WOFF_QKV, p_xh, qkv_b, nullptr, p_qkv, CH3, 256);
    // 3) depthwise 3x3 on qkv, fused q/k norms
    dwnorm_kernel<<<Bsz*CH3, 256, Np*2>>>(p_qkv, qkv_dw_w, qkv_dw_b, p_qkv2, p_inv);
    // 4) split-K partial S
    spart_kernel<<<dim3(SPLITS, NHEADS, Bsz), 256>>>(p_qkv2);
    // 5) reduce + softmax
    attn_reduce_kernel<<<Bsz*NHEADS, 1024>>>(p_inv, temp);
    // 6) attn @ v -> bf16 operand (2 px/thread)
    av_bf16_kernel<<<dim3(Np/512, NHEADS, Bsz), 256>>>(p_qkv2, p_xh);
    // 7) po GEMM + residual -> x1 (fp32)
    gemm_mma_kernel<false><<<dim3(Np/128, 2, Bsz), 256, GEMM_SMEM>>>(
        p_wh + WOFF_PO, p_xh, po_b, x, p_x1, Cdim, 256);
    // 8) LN2 -> bf16 operand
    ln_bf16_kernel<<<Bsz*Np/256, 256>>>(p_x1, n2_w, n2_b, p_xh);
    // 9) FFN project-in (M=1360, pad 1408) -> bf16
    gemm_mma_kernel<true><<<dim3(Np/128, MPAD_PIN/128, Bsz), 256, GEMM_SMEM>>>(
        p_wh + WOFF_PIN, p_xh, pin_b, nullptr, p_pin, HID2, 256);
    // 10) tiled depthwise + GELU gate (bf16)
    dwgate2_kernel<<<Bsz*HID*2, 256, GATE_SMEM>>>(dw_w, dw_b);
    // 11) transpose gate -> operand (K=680 -> 704)
    tconv_kernel<<<dim3(KPAD_G/32, Np/32, Bsz), dim3(32, 8)>>>(p_gate, p_xh, HID, KPAD_G);
    // 12) pout GEMM + residual -> out (fp32)
    gemm_mma_kernel<false><<<dim3(Np/128, 2, Bsz), 256, GEMM_SMEM>>>(
        p_wh + WOFF_POUT, p_xh, pout_b, p_x1, out, Cdim, KPAD_G);
}

// round 10
// speedup vs baseline: 1.2018x; 1.0790x over previous
#include <cuda_runtime.h>
#include <cuda_bf16.h>
#include <cuda_fp16.h>
#include <math.h>
#include <stdint.h>

// ---------------- problem constants ----------------
#define Bsz    4
#define Cdim   256
#define Hh     128
#define Wd     128
#define Np     (Hh*Wd)        // 16384
#define CH3    (3*Cdim)       // 768
#define HID    680
#define HID2   1360
#define NHEADS 8
#define HD     32
#define SPLITS 128
#define CHUNK  (Np/SPLITS)    // 128

#define KPAD_G 704
#define MPAD_PIN 1408

// static power-of-2 scales for fp16 range safety (exactly inverted in epilogue)
#define SC_AV   16.f
#define SC_GATE 512.f

// ---------------- scratch (device globals; no runtime alloc) ----------------
__device__ __align__(16) __nv_bfloat16 g_qkv [(size_t)Bsz*CH3 *Np];
__device__ __align__(16) __nv_bfloat16 g_qkv2[(size_t)Bsz*CH3 *Np];
__device__ float g_inv  [2*Bsz*Cdim];
__device__ float g_spart[(size_t)Bsz*NHEADS*SPLITS*HD*HD];
__device__ float g_attn [Bsz*NHEADS*HD*HD];
__device__ float g_x1   [(size_t)Bsz*Cdim*Np];
__device__ __align__(16) __nv_bfloat16 g_pin [(size_t)Bsz*HID2*Np];
__device__ __align__(16) __nv_bfloat16 g_gate[(size_t)Bsz*HID *Np];

// fp16 operand buffer (X, [b][n][K]) and weights
__device__ __align__(16) __half g_xh[(size_t)Bsz*Np*KPAD_G];
// weights: qkv(768*256) | po(256*256) | pin(1408*256) | pout(256*704)
#define WOFF_QKV  0
#define WOFF_PO   (768*256)
#define WOFF_PIN  (WOFF_PO + 256*256)
#define WOFF_POUT (WOFF_PIN + 1408*256)
#define WTOT      (WOFF_POUT + 256*704)
__device__ __align__(16) __half g_wh[WTOT];

// ---------------- PTX helpers ----------------
__device__ __forceinline__ uint32_t smem_u32(const void* p) {
    uint32_t a;
    asm("{ .reg .u64 t; cvta.to.shared.u64 t, %1; cvt.u32.u64 %0, t; }" : "=r"(a) : "l"(p));
    return a;
}
#define CP_ASYNC16(dst, src) \
    asm volatile("cp.async.cg.shared.global [%0], [%1], 16;" :: "r"(dst), "l"(src) : "memory")
#define CP_COMMIT() asm volatile("cp.async.commit_group;" ::: "memory")
#define CP_WAIT(n)  asm volatile("cp.async.wait_group %0;" :: "n"(n) : "memory")

__device__ __forceinline__ void ldsm4(uint32_t* r, uint32_t addr) {
    asm volatile("ldmatrix.sync.aligned.m8n8.x4.shared.b16 {%0,%1,%2,%3}, [%4];"
                 : "=r"(r[0]), "=r"(r[1]), "=r"(r[2]), "=r"(r[3]) : "r"(addr));
}
// fp16 MMA with fp16 accumulators (2 packed regs)
__device__ __forceinline__ void mma16816h(uint32_t* c, const uint32_t* a, const uint32_t* b) {
    asm volatile(
        "mma.sync.aligned.m16n8k16.row.col.f16.f16.f16.f16 "
        "{%0,%1}, {%2,%3,%4,%5}, {%6,%7}, {%0,%1};"
        : "+r"(c[0]), "+r"(c[1])
        : "r"(a[0]), "r"(a[1]), "r"(a[2]), "r"(a[3]), "r"(b[0]), "r"(b[1]));
}
__device__ __forceinline__ uint32_t packbf2(float a, float b) {
    __nv_bfloat162 h = __floats2bfloat162_rn(a, b);
    return *(uint32_t*)&h;
}
__device__ __forceinline__ uint32_t packh2(float a, float b) {
    __half2 h = __floats2half2_rn(a, b);
    return *(uint32_t*)&h;
}
__device__ __forceinline__ void unpack8(const uint4 v, float* r) {
    float2 f;
    f = __bfloat1622float2(*(const __nv_bfloat162*)&v.x); r[0] = f.x; r[1] = f.y;
    f = __bfloat1622float2(*(const __nv_bfloat162*)&v.y); r[2] = f.x; r[3] = f.y;
    f = __bfloat1622float2(*(const __nv_bfloat162*)&v.z); r[4] = f.x; r[5] = f.y;
    f = __bfloat1622float2(*(const __nv_bfloat162*)&v.w); r[6] = f.x; r[7] = f.y;
}
__device__ __forceinline__ void load_row10(float* r, const __nv_bfloat16* t,
                                           int row, int x0, bool valid) {
    if (!valid) {
        #pragma unroll
        for (int i = 0; i < 10; i++) r[i] = 0.f;
        return;
    }
    const __nv_bfloat16* p = t + row * 128;
    uint4 v = *(const uint4*)(p + x0);
    unpack8(v, r + 1);
    r[0] = (x0 > 0)   ? __bfloat162float(p[x0 - 1]) : 0.f;
    r[9] = (x0 < 120) ? __bfloat162float(p[x0 + 8]) : 0.f;
}

// ================= mma.sync GEMM fp16/fp16-accum (128x128, BK=32, 3-stage) =================
#define TARR_B   10240          // 128 rows x 80 B (32 fp16 + 8 pad)
#define STAGE_B  (2*TARR_B)     // W, X
#define GEMM_SMEM (3*STAGE_B)   // 61440

__device__ __forceinline__ void gemm_issue_tile(
    uint32_t st, int tid, const __half* Wh, const __half* Xh_b,
    int rowBase, int Kpad, int k0)
{
    #pragma unroll
    for (int c = tid; c < 512; c += 256) {
        int r = c >> 2, cc = c & 3;
        uint32_t so = st + r * 80 + cc * 16;
        size_t wo = (size_t)(rowBase + r) * Kpad + k0 + cc * 8;
        size_t xo = (size_t)r * Kpad + k0 + cc * 8;
        CP_ASYNC16(so,          Wh + wo);
        CP_ASYNC16(so + TARR_B, Xh_b + xo);
    }
    CP_COMMIT();
}

template<bool OUT_BF16>
__global__ __launch_bounds__(256) void gemm_mma_kernel(
    const __half* __restrict__ Wh,
    const __half* __restrict__ Xh,
    const float* __restrict__ bias, const float* __restrict__ res,
    void* __restrict__ outp, int M, int Kpad, float isc)
{
    extern __shared__ char smem[];
    const uint32_t sb = smem_u32(smem);
    const int tid = threadIdx.x, lane = tid & 31, wid = tid >> 5;
    const int warpM = wid & 1, warpN = wid >> 1;
    const int rowBase = blockIdx.y * 128, colBase = blockIdx.x * 128, b = blockIdx.z;

    const __half* Xh_b = Xh + ((size_t)b * Np + colBase) * Kpad;

    uint32_t acc[4][4][2];
    #pragma unroll
    for (int i = 0; i < 4; i++)
        #pragma unroll
        for (int j = 0; j < 4; j++) { acc[i][j][0] = 0u; acc[i][j][1] = 0u; }

    const int nk = Kpad >> 5;
    gemm_issue_tile(sb,           tid, Wh, Xh_b, rowBase, Kpad, 0);
    gemm_issue_tile(sb + STAGE_B, tid, Wh, Xh_b, rowBase, Kpad, 32);

    for (int i = 0; i < nk; i++) {
        if (i + 2 < nk) {
            gemm_issue_tile(sb + ((i + 2) % 3) * STAGE_B, tid, Wh, Xh_b,
                            rowBase, Kpad, (i + 2) << 5);
            CP_WAIT(2);
        } else if (i + 1 < nk) {
            CP_WAIT(1);
        } else {
            CP_WAIT(0);
        }
        __syncthreads();

        const uint32_t st = sb + (i % 3) * STAGE_B;
        #pragma unroll
        for (int kk = 0; kk < 2; kk++) {
            uint32_t aA[4][4], bB[4][2];
            const int arow = lane & 15, ahalf = lane >> 4;
            #pragma unroll
            for (int mf = 0; mf < 4; mf++) {
                uint32_t ad = st + (uint32_t)(warpM * 64 + mf * 16 + arow) * 80
                              + kk * 32 + ahalf * 16;
                ldsm4(aA[mf], ad);
            }
            #pragma unroll
            for (int nfp = 0; nfp < 2; nfp++) {
                int nrow = warpN * 32 + nfp * 16 + ((lane >> 4) * 8 + (lane & 7));
                int kb = (lane >> 3) & 1;
                uint32_t bd = st + TARR_B + (uint32_t)nrow * 80 + kk * 32 + kb * 16;
                uint32_t t[4];
                ldsm4(t, bd);
                bB[nfp*2][0] = t[0]; bB[nfp*2][1] = t[1];
                bB[nfp*2+1][0] = t[2]; bB[nfp*2+1][1] = t[3];
            }
            #pragma unroll
            for (int mf = 0; mf < 4; mf++)
                #pragma unroll
                for (int nf = 0; nf < 4; nf++)
                    mma16816h(acc[mf][nf], aA[mf], bB[nf]);
        }
        __syncthreads();
    }

    #pragma unroll
    for (int mf = 0; mf < 4; mf++) {
        int r0 = rowBase + warpM * 64 + mf * 16 + (lane >> 2);
        int r1 = r0 + 8;
        #pragma unroll
        for (int nf = 0; nf < 4; nf++) {
            int c0 = colBase + warpN * 32 + nf * 8 + 2 * (lane & 3);
            float2 lo = __half22float2(*(const __half2*)&acc[mf][nf][0]);
            float2 hi = __half22float2(*(const __half2*)&acc[mf][nf][1]);
            if (r0 < M) {
                float bb = __ldg(bias + r0);
                size_t go = ((size_t)b * M + r0) * Np + c0;
                float v0 = lo.x * isc + bb, v1 = lo.y * isc + bb;
                if (OUT_BF16) {
                    *(uint32_t*)((__nv_bfloat16*)outp + go) = packbf2(v0, v1);
                } else {
                    if (res) { float2 rr = *(const float2*)(res + go); v0 += rr.x; v1 += rr.y; }
                    *(float2*)((float*)outp + go) = make_float2(v0, v1);
                }
            }
            if (r1 < M) {
                float bb = __ldg(bias + r1);
                size_t go = ((size_t)b * M + r1) * Np + c0;
                float v0 = hi.x * isc + bb, v1 = hi.y * isc + bb;
                if (OUT_BF16) {
                    *(uint32_t*)((__nv_bfloat16*)outp + go) = packbf2(v0, v1);
                } else {
                    if (res) { float2 rr = *(const float2*)(res + go); v0 += rr.x; v1 += rr.y; }
                    *(float2*)((float*)outp + go) = make_float2(v0, v1);
                }
            }
        }
    }
}

// ---------------- LayerNorm fused -> transposed fp16 [n][256] ----------------
__global__ __launch_bounds__(256) void ln_fp16_kernel(
    const float* __restrict__ in, const float* __restrict__ w,
    const float* __restrict__ bs, __half* __restrict__ xh)
{
    int pos = blockIdx.x * 256 + threadIdx.x;
    int b = pos / Np, n = pos % Np;
    const float* p = in + (size_t)b * Cdim * Np + n;
    float s = 0.f, sq = 0.f;
    #pragma unroll 8
    for (int c = 0; c < Cdim; c++) { float v = p[(size_t)c * Np]; s += v; sq += v * v; }
    float mu = s * (1.f / Cdim);
    float var = fmaxf(sq * (1.f / Cdim) - mu * mu, 0.f);
    float rs = rsqrtf(var + 1e-5f);
    size_t ro = ((size_t)b * Np + n) * Cdim;
    for (int c0 = 0; c0 < Cdim; c0 += 8) {
        uint32_t ph[4];
        #pragma unroll
        for (int j = 0; j < 4; j++) {
            int c = c0 + 2 * j;
            float y0 = (p[(size_t)c * Np] - mu) * rs * w[c] + bs[c];
            float y1 = (p[(size_t)(c + 1) * Np] - mu) * rs * w[c + 1] + bs[c + 1];
            ph[j] = packh2(y0, y1);
        }
        *(uint4*)(xh + ro + c0) = make_uint4(ph[0], ph[1], ph[2], ph[3]);
    }
}

// ---------------- transpose bf16 [C][N] -> fp16 [n][Kpad] (x SC_GATE) ----------------
__global__ void tconv_kernel(const __nv_bfloat16* __restrict__ src,
                             __half* __restrict__ xh, int Csrc, int Kpad)
{
    __shared__ float t[32][33];
    int c0 = blockIdx.x * 32, n0 = blockIdx.y * 32, b = blockIdx.z;
    int tx = threadIdx.x, ty = threadIdx.y;   // 32 x 8
    #pragma unroll
    for (int ii = 0; ii < 4; ii++) {
        int c = c0 + ty + ii * 8;
        float v = 0.f;
        if (c < Csrc) v = __bfloat162float(src[((size_t)b * Csrc + c) * Np + n0 + tx]);
        t[ty + ii * 8][tx] = v;
    }
    __syncthreads();
    #pragma unroll
    for (int ii = 0; ii < 4; ii++) {
        int n = n0 + ty + ii * 8;
        size_t o = ((size_t)b * Np + n) * Kpad + c0 + tx;
        xh[o] = __float2half(t[tx][ty + ii * 8] * SC_GATE);
    }
}

// ---------------- combined weight fp16 convert ----------------
__global__ void wconv_all_kernel(
    const float* __restrict__ qkv_w, const float* __restrict__ po_w,
    const float* __restrict__ pin_w, const float* __restrict__ pout_w,
    __half* __restrict__ wh)
{
    int idx = blockIdx.x * 256 + threadIdx.x;
    if (idx >= WTOT) return;
    float v;
    if (idx < WOFF_PO) {
        v = qkv_w[idx];
    } else if (idx < WOFF_PIN) {
        v = po_w[idx - WOFF_PO];
    } else if (idx < WOFF_POUT) {
        int l = idx - WOFF_PIN;              // [1408][256]
        v = (l < 1360 * 256) ? pin_w[l] : 0.f;
    } else {
        int l = idx - WOFF_POUT;             // [256][704]
        int r = l / 704, k = l % 704;
        v = (k < 680) ? pout_w[r * 680 + k] : 0.f;
    }
    wh[idx] = __float2half(v);
}

// ---------------- fused depthwise 3x3 + q/k L2-norm, vectorized 8px/thread ----------------
__global__ __launch_bounds__(256) void dwnorm_kernel(
    const __nv_bfloat16* __restrict__ in, const float* __restrict__ w,
    const float* __restrict__ bias, __nv_bfloat16* __restrict__ out,
    float* __restrict__ inv)
{
    extern __shared__ __nv_bfloat16 t[];   // Np bf16 = 32KB
    int bc = blockIdx.x;
    int c = bc % CH3, b = bc / CH3;
    const int tid = threadIdx.x;
    const uint4* ip4 = (const uint4*)(in + ((size_t)b * CH3 + c) * Np);
    uint4* t4 = (uint4*)t;
    #pragma unroll
    for (int i = 0; i < 8; i++)
        t4[i * 256 + tid] = ip4[i * 256 + tid];
    __syncthreads();

    float w00 = w[c*9+0], w01 = w[c*9+1], w02 = w[c*9+2];
    float w10 = w[c*9+3], w11 = w[c*9+4], w12 = w[c*9+5];
    float w20 = w[c*9+6], w21 = w[c*9+7], w22 = w[c*9+8];
    float bb = bias[c];
    __nv_bfloat16* op = out + ((size_t)b * CH3 + c) * Np;
    float ss = 0.f;

    #pragma unroll
    for (int it = 0; it < 8; it++) {
        int base = it * 2048 + tid * 8;
        int h = base >> 7, x0 = base & 127;
        float r0[10], r1[10], r2[10];
        load_row10(r0, t, h - 1, x0, h > 0);
        load_row10(r1, t, h,     x0, true);
        load_row10(r2, t, h + 1, x0, h < 127);
        float o[8];
        #pragma unroll
        for (int i = 0; i < 8; i++) {
            float acc = bb;
            acc += w00 * r0[i] + w01 * r0[i+1] + w02 * r0[i+2];
            acc += w10 * r1[i] + w11 * r1[i+1] + w12 * r1[i+2];
            acc += w20 * r2[i] + w21 * r2[i+1] + w22 * r2[i+2];
            o[i] = acc;
            ss += acc * acc;
        }
        uint4 pk;
        pk.x = packbf2(o[0], o[1]);
        pk.y = packbf2(o[2], o[3]);
        pk.z = packbf2(o[4], o[5]);
        pk.w = packbf2(o[6], o[7]);
        *(uint4*)(op + base) = pk;
    }

    if (c < 2 * Cdim) {
        #pragma unroll
        for (int o2 = 16; o2 > 0; o2 >>= 1) ss += __shfl_xor_sync(0xffffffffu, ss, o2);
        __shared__ float red[8];
        int wid = tid >> 5;
        if ((tid & 31) == 0) red[wid] = ss;
        __syncthreads();
        if (tid == 0) {
            float s = 0.f;
            #pragma unroll
            for (int i = 0; i < 8; i++) s += red[i];
            int which = c >> 8, cc = c & 255;
            inv[which * (Bsz * Cdim) + b * Cdim + cc] = 1.f / fmaxf(sqrtf(s), 1e-12f);
        }
    }
}

// ---------------- split-K partial S (bf16 inputs, fp32 accum) ----------------
__global__ __launch_bounds__(256) void spart_kernel(const __nv_bfloat16* __restrict__ qkv2)
{
    __shared__ float qs[HD][CHUNK + 1];
    __shared__ float ks[HD][CHUNK + 1];
    int split = blockIdx.x, h = blockIdx.y, b = blockIdx.z;
    int n0 = split * CHUNK;
    int tid = threadIdx.x;
    for (int t = tid; t < HD * CHUNK; t += 256) {
        int i = t / CHUNK, nn = t % CHUNK;
        qs[i][nn] = __bfloat162float(qkv2[((size_t)b * CH3 + h * HD + i) * Np + n0 + nn]);
        ks[i][nn] = __bfloat162float(qkv2[((size_t)b * CH3 + Cdim + h * HD + i) * Np + n0 + nn]);
    }
    __syncthreads();
    int i = tid >> 3, j0 = (tid & 7) * 4;
    float a0 = 0.f, a1 = 0.f, a2 = 0.f, a3 = 0.f;
    #pragma unroll 4
    for (int nn = 0; nn < CHUNK; nn++) {
        float qv = qs[i][nn];
        a0 += qv * ks[j0 + 0][nn];
        a1 += qv * ks[j0 + 1][nn];
        a2 += qv * ks[j0 + 2][nn];
        a3 += qv * ks[j0 + 3][nn];
    }
    size_t base = (((size_t)(b * NHEADS + h)) * SPLITS + split) * (HD * HD);
    g_spart[base + i * HD + j0 + 0] = a0;
    g_spart[base + i * HD + j0 + 1] = a1;
    g_spart[base + i * HD + j0 + 2] = a2;
    g_spart[base + i * HD + j0 + 3] = a3;
}

// ---------------- reduce partials + softmax ----------------
__global__ __launch_bounds__(1024) void attn_reduce_kernel(
    const float* __restrict__ inv, const float* __restrict__ temp)
{
    int bh = blockIdx.x;
    int b = bh / NHEADS, h = bh % NHEADS;
    int tid = threadIdx.x;
    int i = tid >> 5, j = tid & 31;
    const float* p = g_spart + (size_t)bh * SPLITS * (HD * HD) + tid;
    float s = 0.f;
    #pragma unroll 4
    for (int sp = 0; sp < SPLITS; sp++) s += p[(size_t)sp * (HD * HD)];
    s *= inv[b * Cdim + h * HD + i] * inv[Bsz * Cdim + b * Cdim + h * HD + j] * temp[h];
    float m = s;
    #pragma unroll
    for (int o = 16; o > 0; o >>= 1) m = fmaxf(m, __shfl_xor_sync(0xffffffffu, m, o));
    float e = expf(s - m);
    float sum = e;
    #pragma unroll
    for (int o = 16; o > 0; o >>= 1) sum += __shfl_xor_sync(0xffffffffu, sum, o);
    g_attn[bh * (HD * HD) + tid] = e / sum;
}

// ---------------- attn @ v -> fp16 operand [n][256], 2 pixels per thread (x SC_AV) ----------------
__global__ __launch_bounds__(256) void av_fp16_kernel(
    const __nv_bfloat16* __restrict__ qkv2, __half* __restrict__ xh)
{
    __shared__ float A[HD * HD];
    int h = blockIdx.y, b = blockIdx.z;
    int bh = b * NHEADS + h;
    int tid = threadIdx.x;
    #pragma unroll
    for (int t = 0; t < 4; t++) A[tid + t * 256] = g_attn[bh * (HD * HD) + tid + t * 256];
    __syncthreads();
    int n0 = blockIdx.x * 512 + tid * 2;       // two adjacent pixels
    float2 vf[HD];
    #pragma unroll
    for (int j = 0; j < HD; j++) {
        __nv_bfloat162 v2 = *(const __nv_bfloat162*)(
            qkv2 + ((size_t)b * CH3 + 2 * Cdim + h * HD + j) * Np + n0);
        vf[j] = __bfloat1622float2(v2);
    }
    float o0[HD], o1[HD];
    #pragma unroll
    for (int i = 0; i < HD; i++) {
        float s0 = 0.f, s1 = 0.f;
        #pragma unroll
        for (int j = 0; j < HD; j++) {
            float a = A[i * HD + j];
            s0 += a * vf[j].x;
            s1 += a * vf[j].y;
        }
        o0[i] = s0 * SC_AV; o1[i] = s1 * SC_AV;
    }
    size_t ob = ((size_t)b * Np + n0) * Cdim + h * HD;
    #pragma unroll
    for (int q = 0; q < 4; q++) {
        uint4 pk0, pk1;
        pk0.x = packh2(o0[q*8+0], o0[q*8+1]); pk0.y = packh2(o0[q*8+2], o0[q*8+3]);
        pk0.z = packh2(o0[q*8+4], o0[q*8+5]); pk0.w = packh2(o0[q*8+6], o0[q*8+7]);
        pk1.x = packh2(o1[q*8+0], o1[q*8+1]); pk1.y = packh2(o1[q*8+2], o1[q*8+3]);
        pk1.z = packh2(o1[q*8+4], o1[q*8+5]); pk1.w = packh2(o1[q*8+6], o1[q*8+7]);
        *(uint4*)(xh + ob + q * 8)        = pk0;
        *(uint4*)(xh + ob + Cdim + q * 8) = pk1;
    }
}

// ---------------- tiled depthwise 3x3 + GELU gating, vectorized 8px/thread ----------------
#define GATE_SMEM (2*66*128*2)   // 33792 B
__global__ __launch_bounds__(256) void dwgate2_kernel(
    const float* __restrict__ w, const float* __restrict__ bias)
{
    extern __shared__ __nv_bfloat16 ts[];
    __nv_bfloat16* t1 = ts;               // 66*128
    __nv_bfloat16* t2 = ts + 66 * 128;
    int blk = blockIdx.x;
    int half = blk & 1;
    int c = (blk >> 1) % HID;
    int b = blk / (2 * HID);
    int h0 = half * 64;
    int tid = threadIdx.x;

    const uint4* s1 = (const uint4*)(g_pin + ((size_t)b * HID2 + c) * Np);
    const uint4* s2 = (const uint4*)(g_pin + ((size_t)b * HID2 + c + HID) * Np);
    uint4* t14 = (uint4*)t1;
    uint4* t24 = (uint4*)t2;
    const uint4 z4 = make_uint4(0u, 0u, 0u, 0u);
    for (int i = tid; i < 66 * 16; i += 256) {
        int r = i >> 4, q = i & 15;
        int grow = h0 - 1 + r;
        bool ok = (grow >= 0) && (grow < Hh);
        t14[i] = ok ? s1[grow * 16 + q] : z4;
        t24[i] = ok ? s2[grow * 16 + q] : z4;
    }
    __syncthreads();

    float a00 = w[c*9+0], a01 = w[c*9+1], a02 = w[c*9+2];
    float a10 = w[c*9+3], a11 = w[c*9+4], a12 = w[c*9+5];
    float a20 = w[c*9+6], a21 = w[c*9+7], a22 = w[c*9+8];
    int c2 = c + HID;
    float b00 = w[c2*9+0], b01 = w[c2*9+1], b02 = w[c2*9+2];
    float b10 = w[c2*9+3], b11 = w[c2*9+4], b12 = w[c2*9+5];
    float b20 = w[c2*9+6], b21 = w[c2*9+7], b22 = w[c2*9+8];
    float ba = bias[c], bg = bias[c2];

    __nv_bfloat16* op = g_gate + ((size_t)b * HID + c) * Np + h0 * Wd;
    #pragma unroll
    for (int it = 0; it < 4; it++) {
        int base = it * 2048 + tid * 8;
        int h = base >> 7, x0 = base & 127;
        float p0[10], p1[10], p2[10];
        float q0[10], q1[10], q2[10];
        load_row10(p0, t1, h,     x0, true);
        load_row10(p1, t1, h + 1, x0, true);
        load_row10(p2, t1, h + 2, x0, true);
        load_row10(q0, t2, h,     x0, true);
        load_row10(q1, t2, h + 1, x0, true);
        load_row10(q2, t2, h + 2, x0, true);
        float o[8];
        #pragma unroll
        for (int i = 0; i < 8; i++) {
            float a = ba, g = bg;
            a += a00 * p0[i] + a01 * p0[i+1] + a02 * p0[i+2];
            a += a10 * p1[i] + a11 * p1[i+1] + a12 * p1[i+2];
            a += a20 * p2[i] + a21 * p2[i+1] + a22 * p2[i+2];
            g += b00 * q0[i] + b01 * q0[i+1] + b02 * q0[i+2];
            g += b10 * q1[i] + b11 * q1[i+1] + b12 * q1[i+2];
            g += b20 * q2[i] + b21 * q2[i+1] + b22 * q2[i+2];
            float gelu = 0.5f * g * (1.f + erff(g * 0.70710678118654752f));
            o[i] = a * gelu;
        }
        uint4 pk;
        pk.x = packbf2(o[0], o[1]);
        pk.y = packbf2(o[2], o[3]);
        pk.z = packbf2(o[4], o[5]);
        pk.w = packbf2(o[6], o[7]);
        *(uint4*)(op + base) = pk;
    }
}

// ---------------- launcher ----------------
extern "C" void kernel_launch(void* const* d_in, const int* in_sizes, int n_in,
                              void* d_out, int out_size)
{
    const float* x        = (const float*)d_in[0];
    const float* n1_w     = (const float*)d_in[1];
    const float* n1_b     = (const float*)d_in[2];
    const float* temp     = (const float*)d_in[3];
    const float* qkv_w    = (const float*)d_in[4];
    const float* qkv_b    = (const float*)d_in[5];
    const float* qkv_dw_w = (const float*)d_in[6];
    const float* qkv_dw_b = (const float*)d_in[7];
    const float* po_w     = (const float*)d_in[8];
    const float* po_b     = (const float*)d_in[9];
    const float* n2_w     = (const float*)d_in[10];
    const float* n2_b     = (const float*)d_in[11];
    const float* pin_w    = (const float*)d_in[12];
    const float* pin_b    = (const float*)d_in[13];
    const float* dw_w     = (const float*)d_in[14];
    const float* dw_b     = (const float*)d_in[15];
    const float* pout_w   = (const float*)d_in[16];
    const float* pout_b   = (const float*)d_in[17];
    float* out = (float*)d_out;

    float *p_inv, *p_x1;
    __nv_bfloat16 *p_qkv, *p_qkv2, *p_pin, *p_gate;
    __half *p_xh, *p_wh;
    cudaGetSymbolAddress((void**)&p_qkv,  g_qkv);
    cudaGetSymbolAddress((void**)&p_qkv2, g_qkv2);
    cudaGetSymbolAddress((void**)&p_inv,  g_inv);
    cudaGetSymbolAddress((void**)&p_x1,   g_x1);
    cudaGetSymbolAddress((void**)&p_pin,  g_pin);
    cudaGetSymbolAddress((void**)&p_gate, g_gate);
    cudaGetSymbolAddress((void**)&p_xh,   g_xh);
    cudaGetSymbolAddress((void**)&p_wh,   g_wh);

    cudaFuncSetAttribute(gemm_mma_kernel<true>,  cudaFuncAttributeMaxDynamicSharedMemorySize, GEMM_SMEM);
    cudaFuncSetAttribute(gemm_mma_kernel<false>, cudaFuncAttributeMaxDynamicSharedMemorySize, GEMM_SMEM);
    cudaFuncSetAttribute(dwnorm_kernel,  cudaFuncAttributeMaxDynamicSharedMemorySize, Np * 2);
    cudaFuncSetAttribute(dwgate2_kernel, cudaFuncAttributeMaxDynamicSharedMemorySize, GATE_SMEM);

    const float ISC_ONE  = 1.f;
    const float ISC_PO   = 1.f / SC_AV;
    const float ISC_POUT = 1.f / SC_GATE;

    // 0) weight conversion
    wconv_all_kernel<<<(WTOT + 255) / 256, 256>>>(qkv_w, po_w, pin_w, pout_w, p_wh);

    // 1) LN1 -> fp16 operand
    ln_fp16_kernel<<<Bsz*Np/256, 256>>>(x, n1_w, n1_b, p_xh);
    // 2) qkv GEMM (M=768, K=256) -> bf16
    gemm_mma_kernel<true><<<dim3(Np/128, 6, Bsz), 256, GEMM_SMEM>>>(
        p_wh + WOFF_QKV, p_xh, qkv_b, nullptr, p_qkv, CH3, 256, ISC_ONE);
    // 3) depthwise 3x3 on qkv, fused q/k norms
    dwnorm_kernel<<<Bsz*CH3, 256, Np*2>>>(p_qkv, qkv_dw_w, qkv_dw_b, p_qkv2, p_inv);
    // 4) split-K partial S
    spart_kernel<<<dim3(SPLITS, NHEADS, Bsz), 256>>>(p_qkv2);
    // 5) reduce + softmax
    attn_reduce_kernel<<<Bsz*NHEADS, 1024>>>(p_inv, temp);
    // 6) attn @ v -> fp16 operand (x16, 2 px/thread)
    av_fp16_kernel<<<dim3(Np/512, NHEADS, Bsz), 256>>>(p_qkv2, p_xh);
    // 7) po GEMM + residual -> x1 (fp32)
    gemm_mma_kernel<false><<<dim3(Np/128, 2, Bsz), 256, GEMM_SMEM>>>(
        p_wh + WOFF_PO, p_xh, po_b, x, p_x1, Cdim, 256, ISC_PO);
    // 8) LN2 -> fp16 operand
    ln_fp16_kernel<<<Bsz*Np/256, 256>>>(p_x1, n2_w, n2_b, p_xh);
    // 9) FFN project-in (M=1360, pad 1408) -> bf16
    gemm_mma_kernel<true><<<dim3(Np/128, MPAD_PIN/128, Bsz), 256, GEMM_SMEM>>>(
        p_wh + WOFF_PIN, p_xh, pin_b, nullptr, p_pin, HID2, 256, ISC_ONE);
    // 10) tiled depthwise + GELU gate (bf16)
    dwgate2_kernel<<<Bsz*HID*2, 256, GATE_SMEM>>>(dw_w, dw_b);
    // 11) transpose gate -> fp16 operand (x512, K=680 -> 704)
    tconv_kernel<<<dim3(KPAD_G/32, Np/32, Bsz), dim3(32, 8)>>>(p_gate, p_xh, HID, KPAD_G);
    // 12) pout GEMM + residual -> out (fp32)
    gemm_mma_kernel<false><<<dim3(Np/128, 2, Bsz), 256, GEMM_SMEM>>>(
        p_wh + WOFF_POUT, p_xh, pout_b, p_x1, out, Cdim, KPAD_G, ISC_POUT);
}